// round 13
// baseline (speedup 1.0000x reference)
#include <cuda_runtime.h>
#include <cuda_fp16.h>
#include <cstdint>

// BitNet MLP, sm_103 generic path (harness compiles at compute_103 — no
// tcgen05). mma.sync.m16n8k16 HMMA + ldmatrix + 3-stage cp.async.
//   gate = (X @ Wg^T) * gs ; up = (X @ Wu^T) * us
//   inter = silu(gate) * up ; out = (inter @ Wd^T) * ds
// fp16 operands (ternary weights exact), fp32 accumulate.
// R12: CTA tile 64m x 128 B-rows, stage 24KB, 3 stages = 72KB -> 3 CTAs/SM
// (6 warps/SMSP). 8 warps as 2m x 4n, warp tile 32x32. Pipeline as R8
// (1 sync per chunk, wait_group 1, prefetch distance 2).

#define HIDDEN 4096
#define INTERDIM 11008
#define MTOK 4096  // BATCH * SEQ

// Static device scratch (allocation-free rule).
__device__ __align__(128) __half g_Xh[(size_t)MTOK * HIDDEN];
__device__ __align__(128) __half g_Wg[(size_t)INTERDIM * HIDDEN];
__device__ __align__(128) __half g_Wu[(size_t)INTERDIM * HIDDEN];
__device__ __align__(128) __half g_Wd[(size_t)HIDDEN * INTERDIM];
__device__ __align__(128) __half g_Inter[(size_t)MTOK * INTERDIM];

// ---------------------------------------------------------------------------
// helpers
// ---------------------------------------------------------------------------
__device__ __forceinline__ uint32_t smem_u32(const void* p) {
    uint32_t a;
    asm("{ .reg .u64 t; cvta.to.shared.u64 t, %1; cvt.u32.u64 %0, t; }"
        : "=r"(a) : "l"(p));
    return a;
}
__device__ __forceinline__ void cpa16(uint32_t dst, const void* src) {
    asm volatile("cp.async.cg.shared.global [%0], [%1], 16;" ::"r"(dst), "l"(src));
}
__device__ __forceinline__ void ldsm_x4(uint32_t* r, uint32_t addr) {
    asm volatile(
        "ldmatrix.sync.aligned.m8n8.x4.shared.b16 {%0,%1,%2,%3}, [%4];"
        : "=r"(r[0]), "=r"(r[1]), "=r"(r[2]), "=r"(r[3]) : "r"(addr));
}
__device__ __forceinline__ void mma16816(float* d, const uint32_t* a,
                                         uint32_t b0, uint32_t b1) {
    asm volatile(
        "mma.sync.aligned.m16n8k16.row.col.f32.f16.f16.f32 "
        "{%0,%1,%2,%3}, {%4,%5,%6,%7}, {%8,%9}, {%0,%1,%2,%3};"
        : "+f"(d[0]), "+f"(d[1]), "+f"(d[2]), "+f"(d[3])
        : "r"(a[0]), "r"(a[1]), "r"(a[2]), "r"(a[3]), "r"(b0), "r"(b1));
}

// ---------------------------------------------------------------------------
// fp32 -> fp16 conversion
// ---------------------------------------------------------------------------
__global__ void cvt_f32_f16(const float* __restrict__ in,
                            __half* __restrict__ out, int n4) {
    int i = blockIdx.x * blockDim.x + threadIdx.x;
    int stride = gridDim.x * blockDim.x;
    for (; i < n4; i += stride) {
        float4 v = reinterpret_cast<const float4*>(in)[i];
        __half2 h0 = __floats2half2_rn(v.x, v.y);
        __half2 h1 = __floats2half2_rn(v.z, v.w);
        uint2 u;
        u.x = *reinterpret_cast<uint32_t*>(&h0);
        u.y = *reinterpret_cast<uint32_t*>(&h1);
        reinterpret_cast<uint2*>(out)[i] = u;
    }
}

// ---------------------------------------------------------------------------
// HGEMM: C[M,N] = A[M,K](row) x B[N,K](row)^T, fp16 in, fp32 accum.
// CTA tile 64 m-rows x 128 B-rows, BK=64 halves (128B rows), 3-stage
// cp.async, 3 CTAs/SM. 8 warps as 2m x 4n. Warp tile 32m x 32n.
// DUAL=1: B rows [0,64)=gate W, [64,128)=up W; warp covers 16 gate + 16 up
//   cols; SwiGLU -> fp16 inter tile 64x64.
// DUAL=0: plain, fp32 out tile 64x128.
// SMEM per stage: A 8KB + B 16KB = 24KB. 3 stages = 72KB -> 3 CTAs/SM.
// Swizzle: 128B rows, 16B slot c stored at (c ^ (r&7)).
// Pipeline (1 sync/chunk): group index == chunk index; at iter k newest
// group is k+1, so wait_group 1 completes chunk k; the sync publishes all
// threads' groups and frees stage (k-1)%3 for the k+2 load.
// ---------------------------------------------------------------------------
#define BK 64
#define STAGE_BYTES 24576   // A 8KB + B 16KB
#define NSTAGE 3
#define SMEM_TOTAL (NSTAGE * STAGE_BYTES)

template <int DUAL>
__global__ __launch_bounds__(256, 3) void hgemm(
    const __half* __restrict__ A, const __half* __restrict__ B0,
    const __half* __restrict__ B1, const float* __restrict__ s0p,
    const float* __restrict__ s1p, __half* __restrict__ outH,
    float* __restrict__ outF, int Ntot, int K) {
    extern __shared__ __align__(128) char smem[];
    const uint32_t smem_base = smem_u32(smem);

    const int tid = threadIdx.x;
    const int lane = tid & 31;
    const int warp = tid >> 5;
    const int wm = warp >> 2;  // 0..1
    const int wn = warp & 3;   // 0..3
    const int m0 = blockIdx.x * 64;

    const __half* Ag = A + (size_t)m0 * K;
    const __half *Bg0, *Bg1;
    if (DUAL) {
        const int nb = blockIdx.y * 64;  // inter cols per CTA = 64
        Bg0 = B0 + (size_t)nb * K;       // gate rows (smem 0..63)
        Bg1 = B1 + (size_t)nb * K;       // up rows   (smem 64..127)
    } else {
        Bg0 = B0 + (size_t)(blockIdx.y * 128) * K;
        Bg1 = B0;
    }

    // Accumulators (warp tile 32x32): [mi][n8-unit][quad]
    float accA[2][4][4];  // single: 4 n8-units ; dual: units 0,1 = gate
    float accU[2][2][4];  // dual only: up
#pragma unroll
    for (int a = 0; a < 2; a++)
#pragma unroll
        for (int b = 0; b < 4; b++)
#pragma unroll
            for (int c = 0; c < 4; c++) accA[a][b][c] = 0.f;
    if (DUAL) {
#pragma unroll
        for (int a = 0; a < 2; a++)
#pragma unroll
            for (int b = 0; b < 2; b++)
#pragma unroll
                for (int c = 0; c < 4; c++) accU[a][b][c] = 0.f;
    }

    const int KT = K / BK;

    // ---- stage loader: A 512 slots + B 1024 slots of 16B, 256 threads ----
    auto load_chunk = [&](int stage, int k) {
        const uint32_t sb = smem_base + stage * STAGE_BYTES;
        const int kcol = k * BK;
#pragma unroll
        for (int i = 0; i < 2; i++) {  // A: 64 rows
            int slot = tid + i * 256;
            int r = slot >> 3, c = slot & 7;
            uint32_t sw = (uint32_t)(r * 128 + ((c ^ (r & 7)) << 4));
            cpa16(sb + sw, Ag + (size_t)r * K + kcol + c * 8);
        }
#pragma unroll
        for (int i = 0; i < 4; i++) {  // B: 128 rows
            int slot = tid + i * 256;
            int r = slot >> 3, c = slot & 7;
            uint32_t sw = (uint32_t)(r * 128 + ((c ^ (r & 7)) << 4));
            const __half* src =
                DUAL ? (r < 64 ? Bg0 + (size_t)r * K : Bg1 + (size_t)(r - 64) * K)
                     : Bg0 + (size_t)r * K;
            cpa16(sb + 8192 + sw, src + kcol + c * 8);
        }
    };

    // Prologue: chunks 0,1 in flight (groups 0,1)
    for (int s = 0; s < 2 && s < KT; s++) {
        load_chunk(s, s);
        asm volatile("cp.async.commit_group;" ::: "memory");
    }

    int st = 0;            // stage of chunk k
    int stp = 2 % NSTAGE;  // stage of chunk k+2
    for (int k = 0; k < KT; k++) {
        // Newest group is k+1 -> wait_group 1 completes chunk k (per-thread);
        // the barrier publishes every thread's groups and retires compute(k-1).
        asm volatile("cp.async.wait_group 1;" ::: "memory");
        __syncthreads();

        if (k + 2 < KT) load_chunk(stp, k + 2);
        asm volatile("cp.async.commit_group;" ::: "memory");  // one group/iter

        const uint32_t sA = smem_base + st * STAGE_BYTES;
        const uint32_t sB = sA + 8192;
#pragma unroll
        for (int ks = 0; ks < 4; ks++) {
            const int kslot = ks * 2 + (lane >> 4);
            uint32_t a[2][4];
#pragma unroll
            for (int mi = 0; mi < 2; mi++) {
                int row = wm * 32 + mi * 16 + (lane & 15);
                ldsm_x4(a[mi], sA + row * 128 + ((kslot ^ (row & 7)) << 4));
            }
            if (DUAL) {
                uint32_t bg[4], bu[4];
                {
                    int rg = wn * 16 + (lane & 15);
                    ldsm_x4(bg, sB + rg * 128 + ((kslot ^ (rg & 7)) << 4));
                    int ru = 64 + wn * 16 + (lane & 15);
                    ldsm_x4(bu, sB + ru * 128 + ((kslot ^ (ru & 7)) << 4));
                }
#pragma unroll
                for (int mi = 0; mi < 2; mi++) {
                    mma16816(accA[mi][0], a[mi], bg[0], bg[2]);
                    mma16816(accA[mi][1], a[mi], bg[1], bg[3]);
                    mma16816(accU[mi][0], a[mi], bu[0], bu[2]);
                    mma16816(accU[mi][1], a[mi], bu[1], bu[3]);
                }
            } else {
                uint32_t b[2][4];
#pragma unroll
                for (int nf = 0; nf < 2; nf++) {
                    int rb = wn * 32 + nf * 16 + (lane & 15);
                    ldsm_x4(b[nf], sB + rb * 128 + ((kslot ^ (rb & 7)) << 4));
                }
#pragma unroll
                for (int mi = 0; mi < 2; mi++)
#pragma unroll
                    for (int nf = 0; nf < 2; nf++) {
                        mma16816(accA[mi][nf * 2 + 0], a[mi], b[nf][0], b[nf][2]);
                        mma16816(accA[mi][nf * 2 + 1], a[mi], b[nf][1], b[nf][3]);
                    }
            }
        }
        st = (st + 1 == NSTAGE) ? 0 : st + 1;
        stp = (stp + 1 == NSTAGE) ? 0 : stp + 1;
    }

    // ---- epilogue ----
    const int g = lane >> 2;   // 0..7 row-in-frag
    const int t = lane & 3;    // 0..3 col-pair
    if (DUAL) {
        const float gs = __ldg(s0p);
        const float us = __ldg(s1p);
        const int nbase = blockIdx.y * 64 + wn * 16;
#pragma unroll
        for (int mi = 0; mi < 2; mi++)
#pragma unroll
            for (int nf = 0; nf < 2; nf++) {
                const int row = m0 + wm * 32 + mi * 16 + g;
                const int col = nbase + nf * 8 + t * 2;
#pragma unroll
                for (int h = 0; h < 2; h++) {  // h=0: row, h=1: row+8
                    float gv0 = accA[mi][nf][h * 2 + 0] * gs;
                    float gv1 = accA[mi][nf][h * 2 + 1] * gs;
                    float uv0 = accU[mi][nf][h * 2 + 0] * us;
                    float uv1 = accU[mi][nf][h * 2 + 1] * us;
                    float v0 = gv0 / (1.0f + __expf(-gv0)) * uv0;
                    float v1 = gv1 / (1.0f + __expf(-gv1)) * uv1;
                    *(__half2*)&outH[(size_t)(row + h * 8) * Ntot + col] =
                        __floats2half2_rn(v0, v1);
                }
            }
    } else {
        const float ds = __ldg(s0p);
        const int nbase = blockIdx.y * 128 + wn * 32;
#pragma unroll
        for (int mi = 0; mi < 2; mi++)
#pragma unroll
            for (int nf = 0; nf < 4; nf++) {
                const int row = m0 + wm * 32 + mi * 16 + g;
                const int col = nbase + nf * 8 + t * 2;
#pragma unroll
                for (int h = 0; h < 2; h++) {
                    float v0 = accA[mi][nf][h * 2 + 0] * ds;
                    float v1 = accA[mi][nf][h * 2 + 1] * ds;
                    *(float2*)&outF[(size_t)(row + h * 8) * Ntot + col] =
                        make_float2(v0, v1);
                }
            }
    }
}

// ---------------------------------------------------------------------------
// Launch
// ---------------------------------------------------------------------------
extern "C" void kernel_launch(void* const* d_in, const int* in_sizes, int n_in,
                              void* d_out, int out_size) {
    (void)in_sizes; (void)n_in; (void)out_size;
    const float* x = (const float*)d_in[0];
    const float* gate_w = (const float*)d_in[1];
    const float* up_w = (const float*)d_in[2];
    const float* down_w = (const float*)d_in[3];
    const float* gs = (const float*)d_in[4];
    const float* us = (const float*)d_in[5];
    const float* ds = (const float*)d_in[6];
    float* out = (float*)d_out;

    __half *Xh, *Wg, *Wu, *Wd, *Ih;
    cudaGetSymbolAddress((void**)&Xh, g_Xh);
    cudaGetSymbolAddress((void**)&Wg, g_Wg);
    cudaGetSymbolAddress((void**)&Wu, g_Wu);
    cudaGetSymbolAddress((void**)&Wd, g_Wd);
    cudaGetSymbolAddress((void**)&Ih, g_Inter);

    cudaFuncSetAttribute(hgemm<1>, cudaFuncAttributeMaxDynamicSharedMemorySize,
                         SMEM_TOTAL);
    cudaFuncSetAttribute(hgemm<0>, cudaFuncAttributeMaxDynamicSharedMemorySize,
                         SMEM_TOTAL);

    // fp32 -> fp16 converts (ternary weights exact in fp16)
    {
        int n4 = (MTOK * HIDDEN) / 4;
        cvt_f32_f16<<<(n4 + 1023) / 1024, 256>>>(x, Xh, n4);
        n4 = (INTERDIM * HIDDEN) / 4;
        cvt_f32_f16<<<(n4 + 1023) / 1024, 256>>>(gate_w, Wg, n4);
        cvt_f32_f16<<<(n4 + 1023) / 1024, 256>>>(up_w, Wu, n4);
        cvt_f32_f16<<<(n4 + 1023) / 1024, 256>>>(down_w, Wd, n4);
    }

    // GEMM1: fused gate/up + SwiGLU -> inter fp16. x = m tiles (fast) for L2
    // reuse of the weight tiles across the wave.
    {
        dim3 grid(MTOK / 64, INTERDIM / 64);  // (64, 172)
        hgemm<1><<<grid, 256, SMEM_TOTAL>>>(Xh, Wg, Wu, gs, us, Ih, nullptr,
                                            INTERDIM, HIDDEN);
    }
    // GEMM2: down projection -> fp32 out
    {
        dim3 grid(MTOK / 64, HIDDEN / 128);  // (64, 32)
        hgemm<0><<<grid, 256, SMEM_TOTAL>>>(Ih, Wd, nullptr, ds, nullptr,
                                            nullptr, out, HIDDEN, INTERDIM);
    }
}

// round 16
// speedup vs baseline: 1.5681x; 1.5681x over previous
#include <cuda_runtime.h>
#include <cuda_fp16.h>
#include <cstdint>

// BitNet MLP, sm_103 generic path (harness compiles at compute_103 — no
// tcgen05). mma.sync.m16n8k16 HMMA + ldmatrix + 3-stage cp.async.
//   gate = (X @ Wg^T) * gs ; up = (X @ Wu^T) * us
//   inter = silu(gate) * up ; out = (inter @ Wd^T) * ds
// fp16 operands (ternary weights exact), fp32 accumulate.
// R14: GEMM identical to best (R8, 2859us). Fused convert kernel rewritten
// with explicit per-range base/stride (R13 resubmit after container failure).

#define HIDDEN 4096
#define INTERDIM 11008
#define MTOK 4096  // BATCH * SEQ

// Static device scratch (allocation-free rule).
__device__ __align__(128) __half g_Xh[(size_t)MTOK * HIDDEN];
__device__ __align__(128) __half g_Wg[(size_t)INTERDIM * HIDDEN];
__device__ __align__(128) __half g_Wu[(size_t)INTERDIM * HIDDEN];
__device__ __align__(128) __half g_Wd[(size_t)HIDDEN * INTERDIM];
__device__ __align__(128) __half g_Inter[(size_t)MTOK * INTERDIM];

// ---------------------------------------------------------------------------
// helpers
// ---------------------------------------------------------------------------
__device__ __forceinline__ uint32_t smem_u32(const void* p) {
    uint32_t a;
    asm("{ .reg .u64 t; cvta.to.shared.u64 t, %1; cvt.u32.u64 %0, t; }"
        : "=r"(a) : "l"(p));
    return a;
}
__device__ __forceinline__ void cpa16(uint32_t dst, const void* src) {
    asm volatile("cp.async.cg.shared.global [%0], [%1], 16;" ::"r"(dst), "l"(src));
}
__device__ __forceinline__ void ldsm_x4(uint32_t* r, uint32_t addr) {
    asm volatile(
        "ldmatrix.sync.aligned.m8n8.x4.shared.b16 {%0,%1,%2,%3}, [%4];"
        : "=r"(r[0]), "=r"(r[1]), "=r"(r[2]), "=r"(r[3]) : "r"(addr));
}
__device__ __forceinline__ void mma16816(float* d, const uint32_t* a,
                                         uint32_t b0, uint32_t b1) {
    asm volatile(
        "mma.sync.aligned.m16n8k16.row.col.f32.f16.f16.f32 "
        "{%0,%1,%2,%3}, {%4,%5,%6,%7}, {%8,%9}, {%0,%1,%2,%3};"
        : "+f"(d[0]), "+f"(d[1]), "+f"(d[2]), "+f"(d[3])
        : "r"(a[0]), "r"(a[1]), "r"(a[2]), "r"(a[3]), "r"(b0), "r"(b1));
}

// ---------------------------------------------------------------------------
// Fused fp32 -> fp16 conversion: one launch for x, gate_w, up_w, down_w.
// Grid is partitioned into four explicit block ranges.
// ---------------------------------------------------------------------------
#define XBLK 4096   // blocks for x      (16.78M elts = 4.19M uint4-quads)
#define WBLK 11008  // blocks per weight (45.09M elts = 11.27M uint4-quads)
#define NX4 ((MTOK * HIDDEN) / 4)
#define NW4 ((INTERDIM * HIDDEN) / 4)

__global__ void cvt_all(const float* __restrict__ x, __half* __restrict__ xo,
                        const float* __restrict__ w0, __half* __restrict__ o0,
                        const float* __restrict__ w1, __half* __restrict__ o1,
                        const float* __restrict__ w2, __half* __restrict__ o2) {
    const float* src;
    __half* dst;
    int n4, base, nblk;
    const int bid = blockIdx.x;
    if (bid < XBLK) {
        src = x;  dst = xo; n4 = NX4; base = 0;               nblk = XBLK;
    } else if (bid < XBLK + WBLK) {
        src = w0; dst = o0; n4 = NW4; base = XBLK;            nblk = WBLK;
    } else if (bid < XBLK + 2 * WBLK) {
        src = w1; dst = o1; n4 = NW4; base = XBLK + WBLK;     nblk = WBLK;
    } else {
        src = w2; dst = o2; n4 = NW4; base = XBLK + 2 * WBLK; nblk = WBLK;
    }
    const int stride = nblk * blockDim.x;
    for (int i = (bid - base) * blockDim.x + threadIdx.x; i < n4; i += stride) {
        float4 v = reinterpret_cast<const float4*>(src)[i];
        __half2 h0 = __floats2half2_rn(v.x, v.y);
        __half2 h1 = __floats2half2_rn(v.z, v.w);
        uint2 u;
        u.x = *reinterpret_cast<uint32_t*>(&h0);
        u.y = *reinterpret_cast<uint32_t*>(&h1);
        reinterpret_cast<uint2*>(dst)[i] = u;
    }
}

// ---------------------------------------------------------------------------
// HGEMM: C[M,N] = A[M,K](row) x B[N,K](row)^T, fp16 in, fp32 accum.
// CTA tile 128 m-rows x 128 B-rows, BK=64 halves (128B rows), 3-stage
// cp.async, 2 CTAs/SM. 8 warps as 4m x 2n. Warp tile 32m x 64n.
// DUAL=1: B rows [0,64)=gate W, [64,128)=up W; SwiGLU -> fp16 inter 128x64.
// DUAL=0: plain, fp32 out tile 128x128.
// SMEM per stage: A 16KB + B 16KB. 3 stages = 96KB -> 2 CTAs/SM.
// Swizzle: 128B rows, 16B slot c stored at (c ^ (r&7)).
// Pipeline (1 sync/chunk): group index == chunk index; at iter k newest
// group is k+1, so wait_group 1 completes chunk k; the sync publishes all
// threads' groups and frees stage (k-1)%3 for the k+2 load.
// ---------------------------------------------------------------------------
#define BK 64
#define STAGE_BYTES 32768
#define NSTAGE 3
#define SMEM_TOTAL (NSTAGE * STAGE_BYTES)

template <int DUAL>
__global__ __launch_bounds__(256, 2) void hgemm(
    const __half* __restrict__ A, const __half* __restrict__ B0,
    const __half* __restrict__ B1, const float* __restrict__ s0p,
    const float* __restrict__ s1p, __half* __restrict__ outH,
    float* __restrict__ outF, int Ntot, int K) {
    extern __shared__ __align__(128) char smem[];
    const uint32_t smem_base = smem_u32(smem);

    const int tid = threadIdx.x;
    const int lane = tid & 31;
    const int warp = tid >> 5;
    const int wm = warp >> 1;  // 0..3
    const int wn = warp & 1;   // 0..1
    const int m0 = blockIdx.x * 128;

    const __half* Ag = A + (size_t)m0 * K;
    const __half *Bg0, *Bg1;
    if (DUAL) {
        const int nb = blockIdx.y * 64;  // inter cols per CTA = 64
        Bg0 = B0 + (size_t)nb * K;       // gate rows
        Bg1 = B1 + (size_t)nb * K;       // up rows
    } else {
        Bg0 = B0 + (size_t)(blockIdx.y * 128) * K;
        Bg1 = B0;
    }

    // Accumulators
    float accA[2][8][4];  // single: [mi][nf8][4] ; dual: [mi][nf4][4] gate
    float accU[2][4][4];  // dual only: up
#pragma unroll
    for (int a = 0; a < 2; a++)
#pragma unroll
        for (int b = 0; b < 8; b++)
#pragma unroll
            for (int c = 0; c < 4; c++) accA[a][b][c] = 0.f;
    if (DUAL) {
#pragma unroll
        for (int a = 0; a < 2; a++)
#pragma unroll
            for (int b = 0; b < 4; b++)
#pragma unroll
                for (int c = 0; c < 4; c++) accU[a][b][c] = 0.f;
    }

    const int KT = K / BK;

    // ---- stage loader: A 1024 slots + B 1024 slots of 16B, 256 threads ----
    auto load_chunk = [&](int stage, int k) {
        const uint32_t sb = smem_base + stage * STAGE_BYTES;
        const int kcol = k * BK;
#pragma unroll
        for (int i = 0; i < 4; i++) {
            int slot = tid + i * 256;
            int r = slot >> 3, c = slot & 7;
            uint32_t sw = (uint32_t)(r * 128 + ((c ^ (r & 7)) << 4));
            cpa16(sb + sw, Ag + (size_t)r * K + kcol + c * 8);
        }
#pragma unroll
        for (int i = 0; i < 4; i++) {
            int slot = tid + i * 256;
            int r = slot >> 3, c = slot & 7;
            uint32_t sw = (uint32_t)(r * 128 + ((c ^ (r & 7)) << 4));
            const __half* src =
                DUAL ? (r < 64 ? Bg0 + (size_t)r * K : Bg1 + (size_t)(r - 64) * K)
                     : Bg0 + (size_t)r * K;
            cpa16(sb + 16384 + sw, src + kcol + c * 8);
        }
    };

    // Prologue: chunks 0,1 in flight (groups 0,1)
    for (int s = 0; s < 2 && s < KT; s++) {
        load_chunk(s, s);
        asm volatile("cp.async.commit_group;" ::: "memory");
    }

    int st = 0;            // stage of chunk k
    int stp = 2 % NSTAGE;  // stage of chunk k+2
    for (int k = 0; k < KT; k++) {
        // Newest group is k+1 -> wait_group 1 completes chunk k (per-thread);
        // the barrier publishes every thread's groups and retires compute(k-1).
        asm volatile("cp.async.wait_group 1;" ::: "memory");
        __syncthreads();

        if (k + 2 < KT) load_chunk(stp, k + 2);
        asm volatile("cp.async.commit_group;" ::: "memory");  // one group/iter

        const uint32_t sA = smem_base + st * STAGE_BYTES;
        const uint32_t sB = sA + 16384;
#pragma unroll
        for (int ks = 0; ks < 4; ks++) {
            const int kslot = ks * 2 + (lane >> 4);
            uint32_t a[2][4];
#pragma unroll
            for (int mi = 0; mi < 2; mi++) {
                int row = wm * 32 + mi * 16 + (lane & 15);
                ldsm_x4(a[mi], sA + row * 128 + ((kslot ^ (row & 7)) << 4));
            }
            if (DUAL) {
                uint32_t bg[2][4], bu[2][4];
#pragma unroll
                for (int nf = 0; nf < 2; nf++) {
                    int rg = wn * 32 + nf * 16 + (lane & 15);
                    ldsm_x4(bg[nf], sB + rg * 128 + ((kslot ^ (rg & 7)) << 4));
                    int ru = 64 + wn * 32 + nf * 16 + (lane & 15);
                    ldsm_x4(bu[nf], sB + ru * 128 + ((kslot ^ (ru & 7)) << 4));
                }
#pragma unroll
                for (int mi = 0; mi < 2; mi++)
#pragma unroll
                    for (int nf = 0; nf < 2; nf++) {
                        mma16816(accA[mi][nf * 2 + 0], a[mi], bg[nf][0], bg[nf][2]);
                        mma16816(accA[mi][nf * 2 + 1], a[mi], bg[nf][1], bg[nf][3]);
                        mma16816(accU[mi][nf * 2 + 0], a[mi], bu[nf][0], bu[nf][2]);
                        mma16816(accU[mi][nf * 2 + 1], a[mi], bu[nf][1], bu[nf][3]);
                    }
            } else {
                uint32_t b[4][4];
#pragma unroll
                for (int nf = 0; nf < 4; nf++) {
                    int rb = wn * 64 + nf * 16 + (lane & 15);
                    ldsm_x4(b[nf], sB + rb * 128 + ((kslot ^ (rb & 7)) << 4));
                }
#pragma unroll
                for (int mi = 0; mi < 2; mi++)
#pragma unroll
                    for (int nf = 0; nf < 4; nf++) {
                        mma16816(accA[mi][nf * 2 + 0], a[mi], b[nf][0], b[nf][2]);
                        mma16816(accA[mi][nf * 2 + 1], a[mi], b[nf][1], b[nf][3]);
                    }
            }
        }
        st = (st + 1 == NSTAGE) ? 0 : st + 1;
        stp = (stp + 1 == NSTAGE) ? 0 : stp + 1;
    }

    // ---- epilogue ----
    const int g = lane >> 2;   // 0..7 row-in-frag
    const int t = lane & 3;    // 0..3 col-pair
    if (DUAL) {
        const float gs = __ldg(s0p);
        const float us = __ldg(s1p);
        const int nbase = blockIdx.y * 64 + wn * 32;
#pragma unroll
        for (int mi = 0; mi < 2; mi++)
#pragma unroll
            for (int nf = 0; nf < 4; nf++) {
                const int row = m0 + wm * 32 + mi * 16 + g;
                const int col = nbase + nf * 8 + t * 2;
#pragma unroll
                for (int h = 0; h < 2; h++) {  // h=0: row, h=1: row+8
                    float gv0 = accA[mi][nf][h * 2 + 0] * gs;
                    float gv1 = accA[mi][nf][h * 2 + 1] * gs;
                    float uv0 = accU[mi][nf][h * 2 + 0] * us;
                    float uv1 = accU[mi][nf][h * 2 + 1] * us;
                    float v0 = gv0 / (1.0f + __expf(-gv0)) * uv0;
                    float v1 = gv1 / (1.0f + __expf(-gv1)) * uv1;
                    *(__half2*)&outH[(size_t)(row + h * 8) * Ntot + col] =
                        __floats2half2_rn(v0, v1);
                }
            }
    } else {
        const float ds = __ldg(s0p);
        const int nbase = blockIdx.y * 128 + wn * 64;
#pragma unroll
        for (int mi = 0; mi < 2; mi++)
#pragma unroll
            for (int nf = 0; nf < 8; nf++) {
                const int row = m0 + wm * 32 + mi * 16 + g;
                const int col = nbase + nf * 8 + t * 2;
#pragma unroll
                for (int h = 0; h < 2; h++) {
                    float v0 = accA[mi][nf][h * 2 + 0] * ds;
                    float v1 = accA[mi][nf][h * 2 + 1] * ds;
                    *(float2*)&outF[(size_t)(row + h * 8) * Ntot + col] =
                        make_float2(v0, v1);
                }
            }
    }
}

// ---------------------------------------------------------------------------
// Launch
// ---------------------------------------------------------------------------
extern "C" void kernel_launch(void* const* d_in, const int* in_sizes, int n_in,
                              void* d_out, int out_size) {
    (void)in_sizes; (void)n_in; (void)out_size;
    const float* x = (const float*)d_in[0];
    const float* gate_w = (const float*)d_in[1];
    const float* up_w = (const float*)d_in[2];
    const float* down_w = (const float*)d_in[3];
    const float* gs = (const float*)d_in[4];
    const float* us = (const float*)d_in[5];
    const float* ds = (const float*)d_in[6];
    float* out = (float*)d_out;

    __half *Xh, *Wg, *Wu, *Wd, *Ih;
    cudaGetSymbolAddress((void**)&Xh, g_Xh);
    cudaGetSymbolAddress((void**)&Wg, g_Wg);
    cudaGetSymbolAddress((void**)&Wu, g_Wu);
    cudaGetSymbolAddress((void**)&Wd, g_Wd);
    cudaGetSymbolAddress((void**)&Ih, g_Inter);

    cudaFuncSetAttribute(hgemm<1>, cudaFuncAttributeMaxDynamicSharedMemorySize,
                         SMEM_TOTAL);
    cudaFuncSetAttribute(hgemm<0>, cudaFuncAttributeMaxDynamicSharedMemorySize,
                         SMEM_TOTAL);

    // One fused convert launch: x + 3 weights (ternary weights exact in fp16)
    {
        dim3 grid(XBLK + 3 * WBLK);  // 37120 blocks
        cvt_all<<<grid, 256>>>(x, Xh, gate_w, Wg, up_w, Wu, down_w, Wd);
    }

    // GEMM1: fused gate/up + SwiGLU -> inter fp16. x = m tiles (fast) for L2
    // reuse of the weight tiles across the wave.
    {
        dim3 grid(MTOK / 128, INTERDIM / 64);  // (32, 172)
        hgemm<1><<<grid, 256, SMEM_TOTAL>>>(Xh, Wg, Wu, gs, us, Ih, nullptr,
                                            INTERDIM, HIDDEN);
    }
    // GEMM2: down projection -> fp32 out
    {
        dim3 grid(MTOK / 128, HIDDEN / 128);  // (32, 32)
        hgemm<0><<<grid, 256, SMEM_TOTAL>>>(Ih, Wd, nullptr, ds, nullptr,
                                            nullptr, out, HIDDEN, INTERDIM);
    }
}